// round 5
// baseline (speedup 1.0000x reference)
#include <cuda_runtime.h>
#include <math.h>
#include <stdint.h>

#define L_  12
#define H_  12
#define D_  768
#define DH_ 64
#define FF_ 3072
#define B_  32
#define S_  256
#define NT_ (B_*S_)   /* 8192 tokens */

/* ---------------- scratch (device globals; no allocations) ---------------- */
__device__ float g_x[NT_*D_];
__device__ float g_q[NT_*D_];
__device__ float g_k[NT_*D_];
__device__ float g_v[NT_*D_];
__device__ float g_a[NT_*D_];
__device__ float g_t[NT_*D_];
__device__ float g_h[(size_t)NT_*FF_];
__device__ float g_sk[64*64];
__device__ float g_pq[32*64];

/* ---------------- block reduction (256 threads) ---------------- */
__device__ __forceinline__ float block_sum_256(float v, float* red) {
    int lane = threadIdx.x & 31, w = threadIdx.x >> 5;
    #pragma unroll
    for (int o = 16; o > 0; o >>= 1) v += __shfl_down_sync(0xffffffffu, v, o);
    if (lane == 0) red[w] = v;
    __syncthreads();
    if (w == 0) {
        float x = (lane < 8) ? red[lane] : 0.f;
        #pragma unroll
        for (int o = 4; o > 0; o >>= 1) x += __shfl_down_sync(0xffffffffu, x, o);
        if (lane == 0) red[32] = x;
    }
    __syncthreads();
    return red[32];
}

/* ---------------- embeddings + LayerNorm ---------------- */
__global__ void embed_ln_kernel(const int* __restrict__ ids, const int* __restrict__ tt,
                                const float* __restrict__ we, const float* __restrict__ pe,
                                const float* __restrict__ te, const float* __restrict__ g,
                                const float* __restrict__ b, float* __restrict__ x)
{
    int row = blockIdx.x;
    int s = row & (S_-1);
    int id = ids[row], t = tt[row];
    __shared__ float buf[D_];
    __shared__ float red[40];
    int tid = threadIdx.x;
    float ps = 0.f;
    #pragma unroll
    for (int i = 0; i < 3; i++) {
        int d = tid + i*256;
        float e = we[(size_t)id*D_ + d] + pe[s*D_ + d] + te[t*D_ + d];
        buf[d] = e; ps += e;
    }
    __syncthreads();
    float mean = block_sum_256(ps, red) * (1.f/D_);
    float pv = 0.f;
    #pragma unroll
    for (int i = 0; i < 3; i++) { int d = tid + i*256; float c = buf[d]-mean; pv += c*c; }
    float var = block_sum_256(pv, red) * (1.f/D_);
    float inv = rsqrtf(var + 1e-12f);
    #pragma unroll
    for (int i = 0; i < 3; i++) {
        int d = tid + i*256;
        x[(size_t)row*D_ + d] = (buf[d]-mean)*inv*g[d] + b[d];
    }
}

/* ---------------- residual add + LayerNorm (in-place on x) ---------------- */
__global__ void add_ln_kernel(float* __restrict__ x, const float* __restrict__ t,
                              const float* __restrict__ g, const float* __restrict__ b)
{
    int row = blockIdx.x;
    __shared__ float buf[D_];
    __shared__ float red[40];
    int tid = threadIdx.x;
    float ps = 0.f;
    #pragma unroll
    for (int i = 0; i < 3; i++) {
        int d = tid + i*256;
        float e = x[(size_t)row*D_ + d] + t[(size_t)row*D_ + d];
        buf[d] = e; ps += e;
    }
    __syncthreads();
    float mean = block_sum_256(ps, red) * (1.f/D_);
    float pv = 0.f;
    #pragma unroll
    for (int i = 0; i < 3; i++) { int d = tid + i*256; float c = buf[d]-mean; pv += c*c; }
    float var = block_sum_256(pv, red) * (1.f/D_);
    float inv = rsqrtf(var + 1e-12f);
    #pragma unroll
    for (int i = 0; i < 3; i++) {
        int d = tid + i*256;
        x[(size_t)row*D_ + d] = (buf[d]-mean)*inv*g[d] + b[d];
    }
}

/* ================= tf32 tensor-core GEMM, 4-stage cp.async =================
 * C[M,N] = A[M,K] @ B[K,N] + bias (opt exact GELU)
 * block 128x128, BK=16, 8 warps (2x4), warp tile 64x32,
 * mma.sync.aligned.m16n8k8 tf32, 4-stage cp.async pipeline (dynamic smem).
 * Requires M%128==0, N%128==0, K%16==0 (true for all shapes here). */

__device__ __forceinline__ void cpasync16(void* smem, const void* gmem) {
    uint32_t s = (uint32_t)__cvta_generic_to_shared(smem);
    asm volatile("cp.async.ca.shared.global [%0], [%1], 16;\n" :: "r"(s), "l"(gmem));
}
__device__ __forceinline__ void cp_commit() { asm volatile("cp.async.commit_group;\n"); }
__device__ __forceinline__ void cp_wait2()  { asm volatile("cp.async.wait_group 2;\n"); }

__device__ __forceinline__ void mma_tf32(float* d, const uint32_t* a, const uint32_t* b) {
    asm volatile(
        "mma.sync.aligned.m16n8k8.row.col.f32.tf32.tf32.f32 "
        "{%0,%1,%2,%3}, {%4,%5,%6,%7}, {%8,%9}, {%0,%1,%2,%3};\n"
        : "+f"(d[0]), "+f"(d[1]), "+f"(d[2]), "+f"(d[3])
        : "r"(a[0]), "r"(a[1]), "r"(a[2]), "r"(a[3]), "r"(b[0]), "r"(b[1]));
}

#define APAD 20    /* As row stride (floats): 16 + 4 */
#define BPAD 136   /* Bs row stride (floats): 128 + 8 */
#define STAGES 4
#define A_ST (128*APAD)          /* floats per A stage: 2560 */
#define B_ST (16*BPAD)           /* floats per B stage: 2176 */
#define SMEM_FLOATS (STAGES*(A_ST + B_ST))
#define SMEM_BYTES  (SMEM_FLOATS*4)   /* 75776 B */

#define AS(st, m, k) smbuf[(st)*A_ST + (m)*APAD + (k)]
#define BS(st, k, n) smbuf[STAGES*A_ST + (st)*B_ST + (k)*BPAD + (n)]

__global__ __launch_bounds__(256, 2)
void sgemm_tf32(const float* __restrict__ A, const float* __restrict__ B,
                const float* __restrict__ bias, float* __restrict__ C,
                int M, int N, int K, int gelu)
{
    extern __shared__ __align__(16) float smbuf[];

    const int tid  = threadIdx.x;
    const int brow = blockIdx.y * 128;
    const int bcol = blockIdx.x * 128;
    const int lane = tid & 31;
    const int wid  = tid >> 5;
    const int g    = lane >> 2;      /* groupID 0..7 */
    const int tg   = lane & 3;       /* thread-in-group 0..3 */
    const int wm   = (wid & 1) * 64;
    const int wn   = (wid >> 1) * 32;

    float acc[4][4][4];
    #pragma unroll
    for (int mt = 0; mt < 4; mt++)
        #pragma unroll
        for (int nt = 0; nt < 4; nt++)
            #pragma unroll
            for (int i = 0; i < 4; i++) acc[mt][nt][i] = 0.f;

    /* stage loader: A tile 128x16 (512 16B chunks), B tile 16x128 (512 chunks) */
    const int am = tid >> 2, akc = (tid & 3) << 2;
    const int am2 = (tid + 256) >> 2, akc2 = ((tid + 256) & 3) << 2;
    const int bk = tid >> 5, bnc = (tid & 31) << 2;
    const int bk2 = (tid + 256) >> 5, bnc2 = ((tid + 256) & 31) << 2;

    #define LOAD_STAGE(st, k0) do {                                                \
        cpasync16(&AS(st, am , akc ), A + (size_t)(brow + am )*K + (k0) + akc );    \
        cpasync16(&AS(st, am2, akc2), A + (size_t)(brow + am2)*K + (k0) + akc2);    \
        cpasync16(&BS(st, bk , bnc ), B + (size_t)((k0) + bk )*N + bcol + bnc );    \
        cpasync16(&BS(st, bk2, bnc2), B + (size_t)((k0) + bk2)*N + bcol + bnc2);    \
        cp_commit();                                                               \
    } while (0)

    const int nk = K >> 4;    /* >= 48 for all shapes here */

    LOAD_STAGE(0, 0);
    LOAD_STAGE(1, 16);
    LOAD_STAGE(2, 32);

    for (int it = 0; it < nk; it++) {
        cp_wait2();                       /* stage it's data resident */
        __syncthreads();
        const int cur = it & 3;
        if (it + 3 < nk) {
            LOAD_STAGE((it + 3) & 3, (it + 3) << 4);
        } else {
            cp_commit();                  /* empty group: keep accounting aligned */
        }

        #pragma unroll
        for (int kk = 0; kk < 16; kk += 8) {
            uint32_t afr[4][4];
            #pragma unroll
            for (int mt = 0; mt < 4; mt++) {
                int m = wm + mt*16;
                afr[mt][0] = __float_as_uint(AS(cur, m + g    , kk + tg    ));
                afr[mt][1] = __float_as_uint(AS(cur, m + g + 8, kk + tg    ));
                afr[mt][2] = __float_as_uint(AS(cur, m + g    , kk + tg + 4));
                afr[mt][3] = __float_as_uint(AS(cur, m + g + 8, kk + tg + 4));
            }
            uint32_t bfr[4][2];
            #pragma unroll
            for (int nt = 0; nt < 4; nt++) {
                int n = wn + nt*8;
                bfr[nt][0] = __float_as_uint(BS(cur, kk + tg    , n + g));
                bfr[nt][1] = __float_as_uint(BS(cur, kk + tg + 4, n + g));
            }
            #pragma unroll
            for (int mt = 0; mt < 4; mt++)
                #pragma unroll
                for (int nt = 0; nt < 4; nt++)
                    mma_tf32(acc[mt][nt], afr[mt], bfr[nt]);
        }
    }

    /* epilogue: bias (+ optional exact GELU), float2 stores */
    #pragma unroll
    for (int mt = 0; mt < 4; mt++) {
        #pragma unroll
        for (int nt = 0; nt < 4; nt++) {
            int row0 = brow + wm + mt*16 + g;
            int col  = bcol + wn + nt*8 + tg*2;
            float b0 = bias[col], b1 = bias[col + 1];
            float c0 = acc[mt][nt][0] + b0;
            float c1 = acc[mt][nt][1] + b1;
            float c2 = acc[mt][nt][2] + b0;
            float c3 = acc[mt][nt][3] + b1;
            if (gelu) {
                c0 = 0.5f*c0*(1.f + erff(c0*0.70710678118654752f));
                c1 = 0.5f*c1*(1.f + erff(c1*0.70710678118654752f));
                c2 = 0.5f*c2*(1.f + erff(c2*0.70710678118654752f));
                c3 = 0.5f*c3*(1.f + erff(c3*0.70710678118654752f));
            }
            *(float2*)(C + (size_t)row0*N + col)       = make_float2(c0, c1);
            *(float2*)(C + (size_t)(row0 + 8)*N + col) = make_float2(c2, c3);
        }
    }
}

/* ---------------- fused attention: online softmax, per (b,h,half) -------- */
__global__ void attention_kernel(const float* __restrict__ q, const float* __restrict__ k,
                                 const float* __restrict__ v, const int* __restrict__ mask,
                                 float* __restrict__ o)
{
    int half = blockIdx.x;
    int h    = blockIdx.y;
    int b    = blockIdx.z;
    int qi   = half*128 + threadIdx.x;
    __shared__ float Ks[64][68];
    __shared__ float Vs[64][68];
    __shared__ float mb[64];

    const size_t base = (size_t)b * S_ * D_ + (size_t)h * DH_;
    float qreg[64];
    #pragma unroll
    for (int d = 0; d < 64; d += 4)
        *(float4*)&qreg[d] = *(const float4*)(q + base + (size_t)qi*D_ + d);
    float acc[64];
    #pragma unroll
    for (int d = 0; d < 64; d++) acc[d] = 0.f;
    float m = -1e30f, l = 0.f;

    int r  = threadIdx.x >> 1;
    int cc = (threadIdx.x & 1) * 32;

    for (int c0 = 0; c0 < S_; c0 += 64) {
        #pragma unroll
        for (int j = 0; j < 32; j += 4) {
            float4 k4 = *(const float4*)(k + base + (size_t)(c0+r)*D_ + cc + j);
            float4 v4 = *(const float4*)(v + base + (size_t)(c0+r)*D_ + cc + j);
            *(float4*)&Ks[r][cc+j] = k4;
            *(float4*)&Vs[r][cc+j] = v4;
        }
        if (threadIdx.x < 64)
            mb[threadIdx.x] = mask[b*S_ + c0 + threadIdx.x] ? 0.f : -10000.f;
        __syncthreads();

        for (int kk = 0; kk < 64; kk++) {
            float s = 0.f;
            #pragma unroll
            for (int d = 0; d < 64; d++) s += qreg[d]*Ks[kk][d];
            s = s*0.125f + mb[kk];
            float nm = fmaxf(m, s);
            float sc = __expf(m - nm);
            float p  = __expf(s - nm);
            l = l*sc + p;
            #pragma unroll
            for (int d = 0; d < 64; d++) acc[d] = acc[d]*sc + p*Vs[kk][d];
            m = nm;
        }
        __syncthreads();
    }
    float inv = 1.f / l;
    #pragma unroll
    for (int d = 0; d < 64; d += 4) {
        float4 o4 = make_float4(acc[d]*inv, acc[d+1]*inv, acc[d+2]*inv, acc[d+3]*inv);
        *(float4*)(o + base + (size_t)qi*D_ + d) = o4;
    }
}

/* ---------------- sense head ---------------- */
__global__ void sense_proj_kernel(const float* __restrict__ sense_emb,
                                  const float* __restrict__ att_Wk, float* __restrict__ sk)
{
    int idx = blockIdx.x*256 + threadIdx.x;
    int j = idx >> 6, a = idx & 63;
    float s = 0.f;
    for (int d = 0; d < D_; d++)
        s += sense_emb[(size_t)j*D_ + d] * att_Wk[(size_t)d*64 + a];
    sk[idx] = s;
}

__global__ void pun_proj_kernel(const float* __restrict__ x, const int* __restrict__ loc,
                                const float* __restrict__ att_Wq, float* __restrict__ pq)
{
    int idx = blockIdx.x*256 + threadIdx.x;
    int b = idx >> 6, a = idx & 63;
    int row = b*S_ + loc[b];
    float s = 0.f;
    for (int d = 0; d < D_; d++)
        s += x[(size_t)row*D_ + d] * att_Wq[(size_t)d*64 + a];
    pq[idx] = s;
}

__global__ void top2_kernel(const float* __restrict__ pq, const float* __restrict__ sk,
                            float* __restrict__ out)
{
    int b = blockIdx.x, j = threadIdx.x;
    __shared__ float sc[64];
    float s = 0.f;
    #pragma unroll 8
    for (int a = 0; a < 64; a++) s += pq[b*64 + a] * sk[j*64 + a];
    sc[j] = s * 0.125f;
    __syncthreads();
    if (j == 0) {
        int i1 = 0; float v1 = sc[0];
        for (int i = 1; i < 64; i++) if (sc[i] > v1) { v1 = sc[i]; i1 = i; }
        int i2 = -1; float v2 = -1e30f;
        for (int i = 0; i < 64; i++) if (i != i1 && sc[i] > v2) { v2 = sc[i]; i2 = i; }
        out[b*2 + 0] = (float)i1;
        out[b*2 + 1] = (float)i2;
    }
}

/* ---------------- launch ---------------- */
extern "C" void kernel_launch(void* const* d_in, const int* in_sizes, int n_in,
                              void* d_out, int out_size)
{
    (void)in_sizes; (void)n_in; (void)out_size;
    const int*   input_ids = (const int*)  d_in[0];
    const int*   token_tt  = (const int*)  d_in[1];
    const int*   attn_mask = (const int*)  d_in[2];
    const int*   location  = (const int*)  d_in[3];
    const float* sense_emb = (const float*)d_in[4];
    const float* word_emb  = (const float*)d_in[5];
    const float* pos_emb   = (const float*)d_in[6];
    const float* type_emb  = (const float*)d_in[7];
    const float* emb_ln_g  = (const float*)d_in[8];
    const float* emb_ln_b  = (const float*)d_in[9];
    const float* Wq  = (const float*)d_in[10]; const float* bq  = (const float*)d_in[11];
    const float* Wk  = (const float*)d_in[12]; const float* bk  = (const float*)d_in[13];
    const float* Wv  = (const float*)d_in[14]; const float* bv  = (const float*)d_in[15];
    const float* Wo  = (const float*)d_in[16]; const float* bo  = (const float*)d_in[17];
    const float* ln1g= (const float*)d_in[18]; const float* ln1b= (const float*)d_in[19];
    const float* W1  = (const float*)d_in[20]; const float* b1  = (const float*)d_in[21];
    const float* W2  = (const float*)d_in[22]; const float* b2  = (const float*)d_in[23];
    const float* ln2g= (const float*)d_in[24]; const float* ln2b= (const float*)d_in[25];
    const float* attWq=(const float*)d_in[26]; const float* attWk=(const float*)d_in[27];
    float* out = (float*)d_out;

    float *x,*q,*k,*v,*a,*t,*h,*sk,*pq;
    cudaGetSymbolAddress((void**)&x,  g_x);
    cudaGetSymbolAddress((void**)&q,  g_q);
    cudaGetSymbolAddress((void**)&k,  g_k);
    cudaGetSymbolAddress((void**)&v,  g_v);
    cudaGetSymbolAddress((void**)&a,  g_a);
    cudaGetSymbolAddress((void**)&t,  g_t);
    cudaGetSymbolAddress((void**)&h,  g_h);
    cudaGetSymbolAddress((void**)&sk, g_sk);
    cudaGetSymbolAddress((void**)&pq, g_pq);

    /* opt-in to >48KB dynamic smem (idempotent; host-side, not captured) */
    cudaFuncSetAttribute(sgemm_tf32, cudaFuncAttributeMaxDynamicSharedMemorySize,
                         SMEM_BYTES);

    embed_ln_kernel<<<NT_, 256>>>(input_ids, token_tt, word_emb, pos_emb, type_emb,
                                  emb_ln_g, emb_ln_b, x);

    dim3 gD(D_/128,  NT_/128);   /* N=768  */
    dim3 gF(FF_/128, NT_/128);   /* N=3072 */

    for (int l = 0; l < L_; l++) {
        size_t wDD = (size_t)l*D_*D_;
        size_t wDF = (size_t)l*D_*FF_;
        sgemm_tf32<<<gD, 256, SMEM_BYTES>>>(x, Wq + wDD, bq + l*D_, q, NT_, D_, D_, 0);
        sgemm_tf32<<<gD, 256, SMEM_BYTES>>>(x, Wk + wDD, bk + l*D_, k, NT_, D_, D_, 0);
        sgemm_tf32<<<gD, 256, SMEM_BYTES>>>(x, Wv + wDD, bv + l*D_, v, NT_, D_, D_, 0);
        attention_kernel<<<dim3(2, H_, B_), 128>>>(q, k, v, attn_mask, a);
        sgemm_tf32<<<gD, 256, SMEM_BYTES>>>(a, Wo + wDD, bo + l*D_, t, NT_, D_, D_, 0);
        add_ln_kernel<<<NT_, 256>>>(x, t, ln1g + l*D_, ln1b + l*D_);
        sgemm_tf32<<<gF, 256, SMEM_BYTES>>>(x, W1 + wDF, b1 + l*FF_, h, NT_, FF_, D_, 1);
        sgemm_tf32<<<gD, 256, SMEM_BYTES>>>(h, W2 + wDF, b2 + l*D_, t, NT_, D_, FF_, 0);
        add_ln_kernel<<<NT_, 256>>>(x, t, ln2g + l*D_, ln2b + l*D_);
    }

    sense_proj_kernel<<<16, 256>>>(sense_emb, attWk, sk);
    pun_proj_kernel<<<8, 256>>>(x, location, attWq, pq);
    top2_kernel<<<B_, 64>>>(pq, sk, out);
}

// round 7
// speedup vs baseline: 1.1554x; 1.1554x over previous
#include <cuda_runtime.h>
#include <math.h>
#include <stdint.h>

#define L_  12
#define H_  12
#define D_  768
#define DH_ 64
#define FF_ 3072
#define B_  32
#define S_  256
#define NT_ (B_*S_)   /* 8192 tokens */

/* ---------------- scratch (device globals; no allocations) ---------------- */
__device__ float g_x[NT_*D_];
__device__ float g_q[NT_*D_];
__device__ float g_k[NT_*D_];
__device__ float g_v[NT_*D_];
__device__ float g_a[NT_*D_];
__device__ float g_t[NT_*D_];
__device__ float g_h[(size_t)NT_*FF_];
__device__ float g_sk[64*64];
__device__ float g_pq[32*64];
/* transposed weights: [l][N][K] so GEMM B-operand is n-major */
__device__ float g_wqT[L_*D_*D_];
__device__ float g_wkT[L_*D_*D_];
__device__ float g_wvT[L_*D_*D_];
__device__ float g_woT[L_*D_*D_];
__device__ float g_w1T[(size_t)L_*D_*FF_];
__device__ float g_w2T[(size_t)L_*D_*FF_];

/* ---------------- tiled transpose: src[z][K][N] -> dst[z][N][K] ----------- */
__global__ void transpose_f32(const float* __restrict__ src, float* __restrict__ dst,
                              int K, int N)
{
    __shared__ float tile[32][33];
    size_t off = (size_t)blockIdx.z * K * N;
    int n0 = blockIdx.x * 32, k0 = blockIdx.y * 32;
    int tx = threadIdx.x, ty = threadIdx.y;
    #pragma unroll
    for (int i = 0; i < 32; i += 8)
        tile[ty + i][tx] = src[off + (size_t)(k0 + ty + i) * N + n0 + tx];
    __syncthreads();
    #pragma unroll
    for (int i = 0; i < 32; i += 8)
        dst[off + (size_t)(n0 + ty + i) * K + k0 + tx] = tile[tx][ty + i];
}

/* ---------------- block reduction (256 threads) ---------------- */
__device__ __forceinline__ float block_sum_256(float v, float* red) {
    int lane = threadIdx.x & 31, w = threadIdx.x >> 5;
    #pragma unroll
    for (int o = 16; o > 0; o >>= 1) v += __shfl_down_sync(0xffffffffu, v, o);
    if (lane == 0) red[w] = v;
    __syncthreads();
    if (w == 0) {
        float x = (lane < 8) ? red[lane] : 0.f;
        #pragma unroll
        for (int o = 4; o > 0; o >>= 1) x += __shfl_down_sync(0xffffffffu, x, o);
        if (lane == 0) red[32] = x;
    }
    __syncthreads();
    return red[32];
}

/* ---------------- embeddings + LayerNorm ---------------- */
__global__ void embed_ln_kernel(const int* __restrict__ ids, const int* __restrict__ tt,
                                const float* __restrict__ we, const float* __restrict__ pe,
                                const float* __restrict__ te, const float* __restrict__ g,
                                const float* __restrict__ b, float* __restrict__ x)
{
    int row = blockIdx.x;
    int s = row & (S_-1);
    int id = ids[row], t = tt[row];
    __shared__ float buf[D_];
    __shared__ float red[40];
    int tid = threadIdx.x;
    float ps = 0.f;
    #pragma unroll
    for (int i = 0; i < 3; i++) {
        int d = tid + i*256;
        float e = we[(size_t)id*D_ + d] + pe[s*D_ + d] + te[t*D_ + d];
        buf[d] = e; ps += e;
    }
    __syncthreads();
    float mean = block_sum_256(ps, red) * (1.f/D_);
    float pv = 0.f;
    #pragma unroll
    for (int i = 0; i < 3; i++) { int d = tid + i*256; float c = buf[d]-mean; pv += c*c; }
    float var = block_sum_256(pv, red) * (1.f/D_);
    float inv = rsqrtf(var + 1e-12f);
    #pragma unroll
    for (int i = 0; i < 3; i++) {
        int d = tid + i*256;
        x[(size_t)row*D_ + d] = (buf[d]-mean)*inv*g[d] + b[d];
    }
}

/* ---------------- residual add + LayerNorm (in-place on x) ---------------- */
__global__ void add_ln_kernel(float* __restrict__ x, const float* __restrict__ t,
                              const float* __restrict__ g, const float* __restrict__ b)
{
    int row = blockIdx.x;
    __shared__ float buf[D_];
    __shared__ float red[40];
    int tid = threadIdx.x;
    float ps = 0.f;
    #pragma unroll
    for (int i = 0; i < 3; i++) {
        int d = tid + i*256;
        float e = x[(size_t)row*D_ + d] + t[(size_t)row*D_ + d];
        buf[d] = e; ps += e;
    }
    __syncthreads();
    float mean = block_sum_256(ps, red) * (1.f/D_);
    float pv = 0.f;
    #pragma unroll
    for (int i = 0; i < 3; i++) { int d = tid + i*256; float c = buf[d]-mean; pv += c*c; }
    float var = block_sum_256(pv, red) * (1.f/D_);
    float inv = rsqrtf(var + 1e-12f);
    #pragma unroll
    for (int i = 0; i < 3; i++) {
        int d = tid + i*256;
        x[(size_t)row*D_ + d] = (buf[d]-mean)*inv*g[d] + b[d];
    }
}

/* ================= tf32 tensor-core GEMM with ldmatrix =================
 * C[M,N] = A[M,K] @ B[K,N] + bias (opt exact GELU).
 * B is supplied TRANSPOSED: BT[N][K] row-major.
 * block 128x128, BK=16, 8 warps (2x4), warp tile 64x32,
 * mma.sync.aligned.m16n8k8 tf32, fragments via ldmatrix (tf32-as-b16 view),
 * 2-stage cp.async double buffer.
 * Requires M%128==0, N%128==0, K%16==0. */

__device__ __forceinline__ void cpasync16(void* smem, const void* gmem) {
    uint32_t s = (uint32_t)__cvta_generic_to_shared(smem);
    asm volatile("cp.async.ca.shared.global [%0], [%1], 16;\n" :: "r"(s), "l"(gmem));
}
__device__ __forceinline__ void cp_commit() { asm volatile("cp.async.commit_group;\n"); }
__device__ __forceinline__ void cp_wait0()  { asm volatile("cp.async.wait_group 0;\n"); }

__device__ __forceinline__ void ldsm_x4(uint32_t* r, uint32_t saddr) {
    asm volatile("ldmatrix.sync.aligned.m8n8.x4.shared.b16 {%0,%1,%2,%3}, [%4];"
                 : "=r"(r[0]), "=r"(r[1]), "=r"(r[2]), "=r"(r[3]) : "r"(saddr));
}
__device__ __forceinline__ void mma_tf32(float* d, const uint32_t* a, const uint32_t* b) {
    asm volatile(
        "mma.sync.aligned.m16n8k8.row.col.f32.tf32.tf32.f32 "
        "{%0,%1,%2,%3}, {%4,%5,%6,%7}, {%8,%9}, {%0,%1,%2,%3};\n"
        : "+f"(d[0]), "+f"(d[1]), "+f"(d[2]), "+f"(d[3])
        : "r"(a[0]), "r"(a[1]), "r"(a[2]), "r"(a[3]), "r"(b[0]), "r"(b[1]));
}

#define PAD 20   /* row stride in floats: 16 + 4 -> ldmatrix phase covers all 32 banks */

__global__ __launch_bounds__(256, 2)
void gemm_tf32_ldsm(const float* __restrict__ A, const float* __restrict__ BT,
                    const float* __restrict__ bias, float* __restrict__ C,
                    int M, int N, int K, int gelu)
{
    __shared__ __align__(16) float As[2][128][PAD];
    __shared__ __align__(16) float Bt[2][128][PAD];

    const int tid  = threadIdx.x;
    const int brow = blockIdx.y * 128;
    const int bcol = blockIdx.x * 128;
    const int lane = tid & 31;
    const int wid  = tid >> 5;
    const int g    = lane >> 2;
    const int tg   = lane & 3;
    const int wm   = (wid & 1) * 64;
    const int wn   = (wid >> 1) * 32;

    /* ldmatrix per-thread row/col selectors (verified fragment mapping):
     * A tiles: r0=(m,k) r1=(m+8,k) r2=(m,k+4) r3=(m+8,k+4)
     *   lanes 0-15  -> &As[m + lane][kk],  lanes 16-31 -> &As[m + lane-16][kk+4]
     * B tiles: r0=(n,k) r1=(n,k+4) r2=(n+8,k) r3=(n+8,k+4)                      */
    const int a_m = lane & 15;
    const int a_k = (lane >> 4) << 2;
    const int b_n = (lane & 7) + ((lane >> 4) << 3);
    const int b_k = ((lane >> 3) & 1) << 2;

    float acc[4][4][4];
    #pragma unroll
    for (int mt = 0; mt < 4; mt++)
        #pragma unroll
        for (int nt = 0; nt < 4; nt++)
            #pragma unroll
            for (int i = 0; i < 4; i++) acc[mt][nt][i] = 0.f;

    /* stage loaders: 128 rows x 16 floats (64B = 4 chunks/row) for both tiles */
    const int lr = tid >> 2, lc = (tid & 3) << 2;

    #define LOAD_STAGE(buf, k0) do {                                                   \
        cpasync16(&As[buf][lr   ][lc], A  + (size_t)(brow + lr     )*K + (k0) + lc);    \
        cpasync16(&As[buf][lr+64][lc], A  + (size_t)(brow + lr + 64)*K + (k0) + lc);    \
        cpasync16(&Bt[buf][lr   ][lc], BT + (size_t)(bcol + lr     )*K + (k0) + lc);    \
        cpasync16(&Bt[buf][lr+64][lc], BT + (size_t)(bcol + lr + 64)*K + (k0) + lc);    \
        cp_commit();                                                                   \
    } while (0)

    LOAD_STAGE(0, 0);

    const int nk = K >> 4;
    for (int it = 0; it < nk; it++) {
        cp_wait0();
        __syncthreads();
        const int cur = it & 1;
        if (it + 1 < nk) LOAD_STAGE(cur ^ 1, (it + 1) << 4);

        #pragma unroll
        for (int kk = 0; kk < 16; kk += 8) {
            uint32_t afr[4][4];
            #pragma unroll
            for (int mt = 0; mt < 4; mt++) {
                uint32_t addr = (uint32_t)__cvta_generic_to_shared(
                    &As[cur][wm + mt*16 + a_m][kk + a_k]);
                ldsm_x4(afr[mt], addr);
            }
            uint32_t bfr[2][4];
            #pragma unroll
            for (int np = 0; np < 2; np++) {
                uint32_t addr = (uint32_t)__cvta_generic_to_shared(
                    &Bt[cur][wn + np*16 + b_n][kk + b_k]);
                ldsm_x4(bfr[np], addr);
            }
            #pragma unroll
            for (int mt = 0; mt < 4; mt++)
                #pragma unroll
                for (int nt = 0; nt < 4; nt++)
                    mma_tf32(acc[mt][nt], afr[mt], &bfr[nt >> 1][(nt & 1) * 2]);
        }
    }

    /* epilogue: bias (+ optional exact GELU), float2 stores */
    #pragma unroll
    for (int mt = 0; mt < 4; mt++) {
        #pragma unroll
        for (int nt = 0; nt < 4; nt++) {
            int row0 = brow + wm + mt*16 + g;
            int col  = bcol + wn + nt*8 + tg*2;
            float b0 = bias[col], b1 = bias[col + 1];
            float c0 = acc[mt][nt][0] + b0;
            float c1 = acc[mt][nt][1] + b1;
            float c2 = acc[mt][nt][2] + b0;
            float c3 = acc[mt][nt][3] + b1;
            if (gelu) {
                c0 = 0.5f*c0*(1.f + erff(c0*0.70710678118654752f));
                c1 = 0.5f*c1*(1.f + erff(c1*0.70710678118654752f));
                c2 = 0.5f*c2*(1.f + erff(c2*0.70710678118654752f));
                c3 = 0.5f*c3*(1.f + erff(c3*0.70710678118654752f));
            }
            *(float2*)(C + (size_t)row0*N + col)       = make_float2(c0, c1);
            *(float2*)(C + (size_t)(row0 + 8)*N + col) = make_float2(c2, c3);
        }
    }
}

/* ---------------- fused attention: online softmax, per (b,h,half) -------- */
__global__ void attention_kernel(const float* __restrict__ q, const float* __restrict__ k,
                                 const float* __restrict__ v, const int* __restrict__ mask,
                                 float* __restrict__ o)
{
    int half = blockIdx.x;
    int h    = blockIdx.y;
    int b    = blockIdx.z;
    int qi   = half*128 + threadIdx.x;
    __shared__ float Ks[64][68];
    __shared__ float Vs[64][68];
    __shared__ float mb[64];

    const size_t base = (size_t)b * S_ * D_ + (size_t)h * DH_;
    float qreg[64];
    #pragma unroll
    for (int d = 0; d < 64; d += 4)
        *(float4*)&qreg[d] = *(const float4*)(q + base + (size_t)qi*D_ + d);
    float acc[64];
    #pragma unroll
    for (int d = 0; d < 64; d++) acc[d] = 0.f;
    float m = -1e30f, l = 0.f;

    int r  = threadIdx.x >> 1;
    int cc = (threadIdx.x & 1) * 32;

    for (int c0 = 0; c0 < S_; c0 += 64) {
        #pragma unroll
        for (int j = 0; j < 32; j += 4) {
            float4 k4 = *(const float4*)(k + base + (size_t)(c0+r)*D_ + cc + j);
            float4 v4 = *(const float4*)(v + base + (size_t)(c0+r)*D_ + cc + j);
            *(float4*)&Ks[r][cc+j] = k4;
            *(float4*)&Vs[r][cc+j] = v4;
        }
        if (threadIdx.x < 64)
            mb[threadIdx.x] = mask[b*S_ + c0 + threadIdx.x] ? 0.f : -10000.f;
        __syncthreads();

        for (int kk = 0; kk < 64; kk++) {
            float s = 0.f;
            #pragma unroll
            for (int d = 0; d < 64; d++) s += qreg[d]*Ks[kk][d];
            s = s*0.125f + mb[kk];
            float nm = fmaxf(m, s);
            float sc = __expf(m - nm);
            float p  = __expf(s - nm);
            l = l*sc + p;
            #pragma unroll
            for (int d = 0; d < 64; d++) acc[d] = acc[d]*sc + p*Vs[kk][d];
            m = nm;
        }
        __syncthreads();
    }
    float inv = 1.f / l;
    #pragma unroll
    for (int d = 0; d < 64; d += 4) {
        float4 o4 = make_float4(acc[d]*inv, acc[d+1]*inv, acc[d+2]*inv, acc[d+3]*inv);
        *(float4*)(o + base + (size_t)qi*D_ + d) = o4;
    }
}

/* ---------------- sense head ---------------- */
__global__ void sense_proj_kernel(const float* __restrict__ sense_emb,
                                  const float* __restrict__ att_Wk, float* __restrict__ sk)
{
    int idx = blockIdx.x*256 + threadIdx.x;
    int j = idx >> 6, a = idx & 63;
    float s = 0.f;
    for (int d = 0; d < D_; d++)
        s += sense_emb[(size_t)j*D_ + d] * att_Wk[(size_t)d*64 + a];
    sk[idx] = s;
}

__global__ void pun_proj_kernel(const float* __restrict__ x, const int* __restrict__ loc,
                                const float* __restrict__ att_Wq, float* __restrict__ pq)
{
    int idx = blockIdx.x*256 + threadIdx.x;
    int b = idx >> 6, a = idx & 63;
    int row = b*S_ + loc[b];
    float s = 0.f;
    for (int d = 0; d < D_; d++)
        s += x[(size_t)row*D_ + d] * att_Wq[(size_t)d*64 + a];
    pq[idx] = s;
}

__global__ void top2_kernel(const float* __restrict__ pq, const float* __restrict__ sk,
                            float* __restrict__ out)
{
    int b = blockIdx.x, j = threadIdx.x;
    __shared__ float sc[64];
    float s = 0.f;
    #pragma unroll 8
    for (int a = 0; a < 64; a++) s += pq[b*64 + a] * sk[j*64 + a];
    sc[j] = s * 0.125f;
    __syncthreads();
    if (j == 0) {
        int i1 = 0; float v1 = sc[0];
        for (int i = 1; i < 64; i++) if (sc[i] > v1) { v1 = sc[i]; i1 = i; }
        int i2 = -1; float v2 = -1e30f;
        for (int i = 0; i < 64; i++) if (i != i1 && sc[i] > v2) { v2 = sc[i]; i2 = i; }
        out[b*2 + 0] = (float)i1;
        out[b*2 + 1] = (float)i2;
    }
}

/* ---------------- launch ---------------- */
extern "C" void kernel_launch(void* const* d_in, const int* in_sizes, int n_in,
                              void* d_out, int out_size)
{
    (void)in_sizes; (void)n_in; (void)out_size;
    const int*   input_ids = (const int*)  d_in[0];
    const int*   token_tt  = (const int*)  d_in[1];
    const int*   attn_mask = (const int*)  d_in[2];
    const int*   location  = (const int*)  d_in[3];
    const float* sense_emb = (const float*)d_in[4];
    const float* word_emb  = (const float*)d_in[5];
    const float* pos_emb   = (const float*)d_in[6];
    const float* type_emb  = (const float*)d_in[7];
    const float* emb_ln_g  = (const float*)d_in[8];
    const float* emb_ln_b  = (const float*)d_in[9];
    const float* Wq  = (const float*)d_in[10]; const float* bq  = (const float*)d_in[11];
    const float* Wk  = (const float*)d_in[12]; const float* bk  = (const float*)d_in[13];
    const float* Wv  = (const float*)d_in[14]; const float* bv  = (const float*)d_in[15];
    const float* Wo  = (const float*)d_in[16]; const float* bo  = (const float*)d_in[17];
    const float* ln1g= (const float*)d_in[18]; const float* ln1b= (const float*)d_in[19];
    const float* W1  = (const float*)d_in[20]; const float* b1  = (const float*)d_in[21];
    const float* W2  = (const float*)d_in[22]; const float* b2  = (const float*)d_in[23];
    const float* ln2g= (const float*)d_in[24]; const float* ln2b= (const float*)d_in[25];
    const float* attWq=(const float*)d_in[26]; const float* attWk=(const float*)d_in[27];
    float* out = (float*)d_out;

    float *x,*q,*k,*v,*a,*t,*h,*sk,*pq;
    float *wqT,*wkT,*wvT,*woT,*w1T,*w2T;
    cudaGetSymbolAddress((void**)&x,  g_x);
    cudaGetSymbolAddress((void**)&q,  g_q);
    cudaGetSymbolAddress((void**)&k,  g_k);
    cudaGetSymbolAddress((void**)&v,  g_v);
    cudaGetSymbolAddress((void**)&a,  g_a);
    cudaGetSymbolAddress((void**)&t,  g_t);
    cudaGetSymbolAddress((void**)&h,  g_h);
    cudaGetSymbolAddress((void**)&sk, g_sk);
    cudaGetSymbolAddress((void**)&pq, g_pq);
    cudaGetSymbolAddress((void**)&wqT, g_wqT);
    cudaGetSymbolAddress((void**)&wkT, g_wkT);
    cudaGetSymbolAddress((void**)&wvT, g_wvT);
    cudaGetSymbolAddress((void**)&woT, g_woT);
    cudaGetSymbolAddress((void**)&w1T, g_w1T);
    cudaGetSymbolAddress((void**)&w2T, g_w2T);

    /* transpose all weights: [l][K][N] -> [l][N][K] */
    {
        dim3 thr(32, 8);
        dim3 gDD(D_/32,  D_/32,  L_);
        dim3 g1 (FF_/32, D_/32,  L_);   /* W1: K=D,  N=FF */
        dim3 g2 (D_/32,  FF_/32, L_);   /* W2: K=FF, N=D  */
        transpose_f32<<<gDD, thr>>>(Wq, wqT, D_, D_);
        transpose_f32<<<gDD, thr>>>(Wk, wkT, D_, D_);
        transpose_f32<<<gDD, thr>>>(Wv, wvT, D_, D_);
        transpose_f32<<<gDD, thr>>>(Wo, woT, D_, D_);
        transpose_f32<<<g1,  thr>>>(W1, w1T, D_, FF_);
        transpose_f32<<<g2,  thr>>>(W2, w2T, FF_, D_);
    }

    embed_ln_kernel<<<NT_, 256>>>(input_ids, token_tt, word_emb, pos_emb, type_emb,
                                  emb_ln_g, emb_ln_b, x);

    dim3 gD(D_/128,  NT_/128);   /* N=768  */
    dim3 gF(FF_/128, NT_/128);   /* N=3072 */

    for (int l = 0; l < L_; l++) {
        size_t wDD = (size_t)l*D_*D_;
        size_t wDF = (size_t)l*D_*FF_;
        gemm_tf32_ldsm<<<gD, 256>>>(x, wqT + wDD, bq + l*D_, q, NT_, D_, D_, 0);
        gemm_tf32_ldsm<<<gD, 256>>>(x, wkT + wDD, bk + l*D_, k, NT_, D_, D_, 0);
        gemm_tf32_ldsm<<<gD, 256>>>(x, wvT + wDD, bv + l*D_, v, NT_, D_, D_, 0);
        attention_kernel<<<dim3(2, H_, B_), 128>>>(q, k, v, attn_mask, a);
        gemm_tf32_ldsm<<<gD, 256>>>(a, woT + wDD, bo + l*D_, t, NT_, D_, D_, 0);
        add_ln_kernel<<<NT_, 256>>>(x, t, ln1g + l*D_, ln1b + l*D_);
        gemm_tf32_ldsm<<<gF, 256>>>(x, w1T + wDF, b1 + l*FF_, h, NT_, FF_, D_, 1);
        gemm_tf32_ldsm<<<gD, 256>>>(h, w2T + wDF, b2 + l*D_, t, NT_, D_, FF_, 0);
        add_ln_kernel<<<NT_, 256>>>(x, t, ln2g + l*D_, ln2b + l*D_);
    }

    sense_proj_kernel<<<16, 256>>>(sense_emb, attWk, sk);
    pun_proj_kernel<<<8, 256>>>(x, location, attWq, pq);
    top2_kernel<<<B_, 64>>>(pq, sk, out);
}